// round 4
// baseline (speedup 1.0000x reference)
#include <cuda_runtime.h>
#include <cuda_fp16.h>
#include <cstdint>

// ============================= problem constants =============================
#define MDIM 8192
#define NDIM 4096
#define KDIM 4096
#define W_ELEMS (NDIM * KDIM)
#define X_ELEMS (MDIM * KDIM)
#define EPSV 1e-5f

// ============================= GEMM tiling ===================================
#define BM 128
#define BN 256
#define BK 64                    // halves per k-stage = 128 bytes per row
#define STAGES 4
#define KT (KDIM / BK)           // 64 k-stages
#define A_STAGE_BYTES (BM * BK * 2)   // 16384
#define B_STAGE_BYTES (BN * BK * 2)   // 32768
#define SMEM_TOTAL (STAGES * (A_STAGE_BYTES + B_STAGE_BYTES))   // 196608

// XOR swizzle for 128B rows: 16B chunk index ^= row%8
#define SWZ(byte) ((byte) ^ (((byte) >> 3) & 0x70))

// ============================= device scratch ================================
__device__ __half  g_Wqh[W_ELEMS];   // round(W/(mean|W|+eps)) as fp16 (exact ints)
__device__ __half  g_xh[X_ELEMS];    // x cast to fp16
__device__ double  g_partial[1024];
__device__ float   g_scale;          // mean(|W|)
__device__ float   g_den;            // mean(|W|) + eps

// ============================= asm helpers ===================================
__device__ __forceinline__ uint32_t smem_u32(const void* p) {
    uint32_t a;
    asm("{ .reg .u64 t; cvta.to.shared.u64 t, %1; cvt.u32.u64 %0, t; }" : "=r"(a) : "l"(p));
    return a;
}

__device__ __forceinline__ void cp_async16(uint32_t dst, const void* src) {
    asm volatile("cp.async.cg.shared.global [%0], [%1], 16;" :: "r"(dst), "l"(src));
}
#define CP_COMMIT() asm volatile("cp.async.commit_group;" ::: "memory")
#define CP_WAIT(N)  asm volatile("cp.async.wait_group %0;" :: "n"(N) : "memory")

__device__ __forceinline__ void ldm_x4(uint32_t& r0, uint32_t& r1, uint32_t& r2, uint32_t& r3,
                                       uint32_t addr) {
    asm volatile("ldmatrix.sync.aligned.m8n8.x4.shared.b16 {%0,%1,%2,%3}, [%4];"
                 : "=r"(r0), "=r"(r1), "=r"(r2), "=r"(r3) : "r"(addr));
}

__device__ __forceinline__ void mma_16816(float& c0, float& c1, float& c2, float& c3,
                                          uint32_t a0, uint32_t a1, uint32_t a2, uint32_t a3,
                                          uint32_t b0, uint32_t b1) {
    asm volatile("mma.sync.aligned.m16n8k16.row.col.f32.f16.f16.f32 "
                 "{%0,%1,%2,%3}, {%4,%5,%6,%7}, {%8,%9}, {%0,%1,%2,%3};"
                 : "+f"(c0), "+f"(c1), "+f"(c2), "+f"(c3)
                 : "r"(a0), "r"(a1), "r"(a2), "r"(a3), "r"(b0), "r"(b1));
}

// ============================= preprocessing =================================
__global__ void k_reduce1(const float* __restrict__ W) {
    __shared__ double sdata[256];
    double s = 0.0;
    for (int i = blockIdx.x * 256 + threadIdx.x; i < W_ELEMS; i += 256 * 1024)
        s += (double)fabsf(W[i]);
    sdata[threadIdx.x] = s;
    __syncthreads();
    for (int o = 128; o > 0; o >>= 1) {
        if (threadIdx.x < o) sdata[threadIdx.x] += sdata[threadIdx.x + o];
        __syncthreads();
    }
    if (threadIdx.x == 0) g_partial[blockIdx.x] = sdata[0];
}

__global__ void k_reduce2() {
    __shared__ double sdata[256];
    double s = 0.0;
    for (int i = threadIdx.x; i < 1024; i += 256) s += g_partial[i];
    sdata[threadIdx.x] = s;
    __syncthreads();
    for (int o = 128; o > 0; o >>= 1) {
        if (threadIdx.x < o) sdata[threadIdx.x] += sdata[threadIdx.x + o];
        __syncthreads();
    }
    if (threadIdx.x == 0) {
        float sc = (float)(sdata[0] / (double)W_ELEMS);
        g_scale = sc;
        g_den = sc + EPSV;
    }
}

// Wq = round_half_even(W / (mean|W|+eps)) -> fp16 (exact: small integers)
__global__ void k_quant(const float4* __restrict__ W4) {
    const float den = g_den;
    __half2* out2 = reinterpret_cast<__half2*>(g_Wqh);
    const int n4 = W_ELEMS / 4;
    for (int i = blockIdx.x * blockDim.x + threadIdx.x; i < n4; i += gridDim.x * blockDim.x) {
        float4 w = W4[i];
        out2[2 * i + 0] = __floats2half2_rn(rintf(w.x / den), rintf(w.y / den));
        out2[2 * i + 1] = __floats2half2_rn(rintf(w.z / den), rintf(w.w / den));
    }
}

// x -> fp16
__global__ void k_xcvt(const float4* __restrict__ X4) {
    __half2* out2 = reinterpret_cast<__half2*>(g_xh);
    const int n4 = X_ELEMS / 4;
    for (int i = blockIdx.x * blockDim.x + threadIdx.x; i < n4; i += gridDim.x * blockDim.x) {
        float4 v = X4[i];
        out2[2 * i + 0] = __floats2half2_rn(v.x, v.y);
        out2[2 * i + 1] = __floats2half2_rn(v.z, v.w);
    }
}

// ============================= GEMM kernel ===================================
// CTA 128x256, 8 warps (2M x 4N), warp tile 64x64, 4-stage cp.async pipeline
__global__ void __launch_bounds__(256, 1) bitlinear_gemm(float* __restrict__ out) {
    extern __shared__ char smem[];
    const uint32_t sb = smem_u32(smem);
    const int tid = threadIdx.x;
    const int wid = tid >> 5;
    const int lid = tid & 31;

    const int m0 = blockIdx.y * BM;
    const int n0 = blockIdx.x * BN;
    const int warp_m = (wid >> 2) * 64;   // 2 warps in M
    const int warp_n = (wid & 3) * 64;    // 4 warps in N

    const __half* __restrict__ gA = g_xh;
    const __half* __restrict__ gB = g_Wqh;

    // ---- stage loader: A = 1024 x 16B chunks, B = 2048 x 16B; 256 threads ----
    auto load_stage = [&](int slot, int kt) {
        const uint32_t sA = sb + slot * A_STAGE_BYTES;
        const uint32_t sBb = sb + STAGES * A_STAGE_BYTES + slot * B_STAGE_BYTES;
        const int kh = kt * BK;   // k offset in halves
#pragma unroll
        for (int i = 0; i < 4; i++) {
            const int ch = tid + i * 256;
            const int row = ch >> 3;
            const int cc = ch & 7;
            cp_async16(sA + SWZ(row * 128 + cc * 16),
                       gA + (size_t)(m0 + row) * KDIM + kh + cc * 8);
        }
#pragma unroll
        for (int i = 0; i < 8; i++) {
            const int ch = tid + i * 256;
            const int row = ch >> 3;
            const int cc = ch & 7;
            cp_async16(sBb + SWZ(row * 128 + cc * 16),
                       gB + (size_t)(n0 + row) * KDIM + kh + cc * 8);
        }
    };

    float acc[4][8][4];
#pragma unroll
    for (int mi = 0; mi < 4; mi++)
#pragma unroll
        for (int ni = 0; ni < 8; ni++)
#pragma unroll
            for (int q = 0; q < 4; q++) acc[mi][ni][q] = 0.0f;

    // prologue: fill STAGES-1 stages
#pragma unroll
    for (int s = 0; s < STAGES - 1; s++) {
        load_stage(s, s);
        CP_COMMIT();
    }

    // ldmatrix lane addressing
    const int a_row = lid & 15;            // row within 16-row tile
    const int a_khalf = (lid >> 4) * 8;    // 0 or 8 (k halves)
    const int b_nrow = ((lid >> 4) * 8) + (lid & 7);  // row within 16-n block
    const int b_khalf = ((lid >> 3) & 1) * 8;

    for (int kt = 0; kt < KT; kt++) {
        CP_WAIT(STAGES - 2);
        __syncthreads();

        const int nt = kt + STAGES - 1;
        if (nt < KT) load_stage(nt % STAGES, nt);
        CP_COMMIT();

        const int slot = kt % STAGES;
        const uint32_t sA = sb + slot * A_STAGE_BYTES;
        const uint32_t sBb = sb + STAGES * A_STAGE_BYTES + slot * B_STAGE_BYTES;

#pragma unroll
        for (int kk = 0; kk < 4; kk++) {        // 4 k-steps of 16
            const int kc = kk * 16;             // k half offset within stage
            uint32_t a[4][4];
#pragma unroll
            for (int mi = 0; mi < 4; mi++) {
                const int row = warp_m + mi * 16 + a_row;
                ldm_x4(a[mi][0], a[mi][1], a[mi][2], a[mi][3],
                       sA + SWZ(row * 128 + (kc + a_khalf) * 2));
            }
            uint32_t b[8][2];
#pragma unroll
            for (int j = 0; j < 4; j++) {       // each x4 covers 2 n-tiles
                const int row = warp_n + j * 16 + b_nrow;
                uint32_t r0, r1, r2, r3;
                ldm_x4(r0, r1, r2, r3,
                       sBb + SWZ(row * 128 + (kc + b_khalf) * 2));
                b[2 * j + 0][0] = r0; b[2 * j + 0][1] = r1;
                b[2 * j + 1][0] = r2; b[2 * j + 1][1] = r3;
            }
#pragma unroll
            for (int mi = 0; mi < 4; mi++)
#pragma unroll
                for (int ni = 0; ni < 8; ni++)
                    mma_16816(acc[mi][ni][0], acc[mi][ni][1], acc[mi][ni][2], acc[mi][ni][3],
                              a[mi][0], a[mi][1], a[mi][2], a[mi][3],
                              b[ni][0], b[ni][1]);
        }
        __syncthreads();
    }

    // ---- epilogue: scale by mean|W| and store ----
    const float sc = g_scale;
    const int er = lid >> 2;         // 0..7
    const int ec = (lid & 3) * 2;    // 0,2,4,6
#pragma unroll
    for (int mi = 0; mi < 4; mi++) {
        const int m_lo = m0 + warp_m + mi * 16 + er;
#pragma unroll
        for (int ni = 0; ni < 8; ni++) {
            const int n = n0 + warp_n + ni * 8 + ec;
            float2 v0 = make_float2(acc[mi][ni][0] * sc, acc[mi][ni][1] * sc);
            float2 v1 = make_float2(acc[mi][ni][2] * sc, acc[mi][ni][3] * sc);
            *reinterpret_cast<float2*>(out + (size_t)m_lo * NDIM + n) = v0;
            *reinterpret_cast<float2*>(out + (size_t)(m_lo + 8) * NDIM + n) = v1;
        }
    }
}

// ============================= host launch ===================================
extern "C" void kernel_launch(void* const* d_in, const int* in_sizes, int n_in,
                              void* d_out, int out_size) {
    const float* x = (const float*)d_in[0];
    const float* W = (const float*)d_in[1];
    float* out = (float*)d_out;

    k_reduce1<<<1024, 256>>>(W);
    k_reduce2<<<1, 256>>>();
    k_quant<<<2048, 256>>>((const float4*)W);
    k_xcvt<<<4096, 256>>>((const float4*)x);

    (void)cudaFuncSetAttribute(bitlinear_gemm, cudaFuncAttributeMaxDynamicSharedMemorySize, SMEM_TOTAL);
    bitlinear_gemm<<<dim3(NDIM / BN, MDIM / BM), 256, SMEM_TOTAL>>>(out);
}

// round 5
// speedup vs baseline: 1.0701x; 1.0701x over previous
#include <cuda_runtime.h>
#include <cuda_fp16.h>
#include <cstdint>

// ============================= problem constants =============================
#define MDIM 8192
#define NDIM 4096
#define KDIM 4096
#define W_ELEMS (NDIM * KDIM)
#define X_ELEMS (MDIM * KDIM)
#define EPSV 1e-5f

// ============================= GEMM tiling ===================================
// CTA 128x128, 4 warps (2M x 2N), warp tile 64x64, 3-stage cp.async pipeline,
// 2 CTAs/SM for sync/wait overlap.
#define BM 128
#define BN 128
#define BK 64                    // halves per k-stage = 128 bytes per row
#define STAGES 3
#define KT (KDIM / BK)           // 64 k-stages
#define A_STAGE_BYTES (BM * BK * 2)   // 16384
#define B_STAGE_BYTES (BN * BK * 2)   // 16384
#define SMEM_TOTAL (STAGES * (A_STAGE_BYTES + B_STAGE_BYTES))   // 98304

// XOR swizzle for 128B rows: 16B chunk index ^= row%8
#define SWZ(byte) ((byte) ^ (((byte) >> 3) & 0x70))

// ============================= device scratch ================================
__device__ __half  g_Wqh[W_ELEMS];   // round(W/(mean|W|+eps)) as fp16 (exact ints)
__device__ __half  g_xh[X_ELEMS];    // x cast to fp16
__device__ double  g_partial[1024];
__device__ float   g_scale;          // mean(|W|)
__device__ float   g_den;            // mean(|W|) + eps

// ============================= asm helpers ===================================
__device__ __forceinline__ uint32_t smem_u32(const void* p) {
    uint32_t a;
    asm("{ .reg .u64 t; cvta.to.shared.u64 t, %1; cvt.u32.u64 %0, t; }" : "=r"(a) : "l"(p));
    return a;
}

__device__ __forceinline__ void cp_async16(uint32_t dst, const void* src) {
    asm volatile("cp.async.cg.shared.global [%0], [%1], 16;" :: "r"(dst), "l"(src));
}
#define CP_COMMIT() asm volatile("cp.async.commit_group;" ::: "memory")
#define CP_WAIT(N)  asm volatile("cp.async.wait_group %0;" :: "n"(N) : "memory")

__device__ __forceinline__ void ldm_x4(uint32_t& r0, uint32_t& r1, uint32_t& r2, uint32_t& r3,
                                       uint32_t addr) {
    asm volatile("ldmatrix.sync.aligned.m8n8.x4.shared.b16 {%0,%1,%2,%3}, [%4];"
                 : "=r"(r0), "=r"(r1), "=r"(r2), "=r"(r3) : "r"(addr));
}

__device__ __forceinline__ void mma_16816(float& c0, float& c1, float& c2, float& c3,
                                          uint32_t a0, uint32_t a1, uint32_t a2, uint32_t a3,
                                          uint32_t b0, uint32_t b1) {
    asm volatile("mma.sync.aligned.m16n8k16.row.col.f32.f16.f16.f32 "
                 "{%0,%1,%2,%3}, {%4,%5,%6,%7}, {%8,%9}, {%0,%1,%2,%3};"
                 : "+f"(c0), "+f"(c1), "+f"(c2), "+f"(c3)
                 : "r"(a0), "r"(a1), "r"(a2), "r"(a3), "r"(b0), "r"(b1));
}

// ============================= preprocessing =================================
__global__ void k_reduce1(const float* __restrict__ W) {
    __shared__ double sdata[256];
    double s = 0.0;
    for (int i = blockIdx.x * 256 + threadIdx.x; i < W_ELEMS; i += 256 * 1024)
        s += (double)fabsf(W[i]);
    sdata[threadIdx.x] = s;
    __syncthreads();
    for (int o = 128; o > 0; o >>= 1) {
        if (threadIdx.x < o) sdata[threadIdx.x] += sdata[threadIdx.x + o];
        __syncthreads();
    }
    if (threadIdx.x == 0) g_partial[blockIdx.x] = sdata[0];
}

__global__ void k_reduce2() {
    __shared__ double sdata[256];
    double s = 0.0;
    for (int i = threadIdx.x; i < 1024; i += 256) s += g_partial[i];
    sdata[threadIdx.x] = s;
    __syncthreads();
    for (int o = 128; o > 0; o >>= 1) {
        if (threadIdx.x < o) sdata[threadIdx.x] += sdata[threadIdx.x + o];
        __syncthreads();
    }
    if (threadIdx.x == 0) {
        float sc = (float)(sdata[0] / (double)W_ELEMS);
        g_scale = sc;
        g_den = sc + EPSV;
    }
}

// Wq = round_half_even(W / (mean|W|+eps)) -> fp16 (exact: small integers)
__global__ void k_quant(const float4* __restrict__ W4) {
    const float den = g_den;
    __half2* out2 = reinterpret_cast<__half2*>(g_Wqh);
    const int n4 = W_ELEMS / 4;
    for (int i = blockIdx.x * blockDim.x + threadIdx.x; i < n4; i += gridDim.x * blockDim.x) {
        float4 w = W4[i];
        out2[2 * i + 0] = __floats2half2_rn(rintf(w.x / den), rintf(w.y / den));
        out2[2 * i + 1] = __floats2half2_rn(rintf(w.z / den), rintf(w.w / den));
    }
}

// x -> fp16
__global__ void k_xcvt(const float4* __restrict__ X4) {
    __half2* out2 = reinterpret_cast<__half2*>(g_xh);
    const int n4 = X_ELEMS / 4;
    for (int i = blockIdx.x * blockDim.x + threadIdx.x; i < n4; i += gridDim.x * blockDim.x) {
        float4 v = X4[i];
        out2[2 * i + 0] = __floats2half2_rn(v.x, v.y);
        out2[2 * i + 1] = __floats2half2_rn(v.z, v.w);
    }
}

// ============================= GEMM kernel ===================================
__global__ void __launch_bounds__(128, 2) bitlinear_gemm(float* __restrict__ out) {
    extern __shared__ char smem[];
    const uint32_t sb = smem_u32(smem);
    const int tid = threadIdx.x;
    const int wid = tid >> 5;
    const int lid = tid & 31;

    const int m0 = blockIdx.y * BM;
    const int n0 = blockIdx.x * BN;
    const int warp_m = (wid >> 1) * 64;   // 2 warps in M
    const int warp_n = (wid & 1) * 64;    // 2 warps in N

    const __half* __restrict__ gA = g_xh;
    const __half* __restrict__ gB = g_Wqh;

    // ---- stage loader: A = 1024 x 16B chunks, B = 1024; 128 threads x8 ----
    auto load_stage = [&](int slot, int kt) {
        const uint32_t sA = sb + slot * A_STAGE_BYTES;
        const uint32_t sBb = sb + STAGES * A_STAGE_BYTES + slot * B_STAGE_BYTES;
        const int kh = kt * BK;   // k offset in halves
#pragma unroll
        for (int i = 0; i < 8; i++) {
            const int ch = tid + i * 128;
            const int row = ch >> 3;
            const int cc = ch & 7;
            cp_async16(sA + SWZ(row * 128 + cc * 16),
                       gA + (size_t)(m0 + row) * KDIM + kh + cc * 8);
        }
#pragma unroll
        for (int i = 0; i < 8; i++) {
            const int ch = tid + i * 128;
            const int row = ch >> 3;
            const int cc = ch & 7;
            cp_async16(sBb + SWZ(row * 128 + cc * 16),
                       gB + (size_t)(n0 + row) * KDIM + kh + cc * 8);
        }
    };

    float acc[4][8][4];
#pragma unroll
    for (int mi = 0; mi < 4; mi++)
#pragma unroll
        for (int ni = 0; ni < 8; ni++)
#pragma unroll
            for (int q = 0; q < 4; q++) acc[mi][ni][q] = 0.0f;

    // prologue: fill STAGES-1 stages
#pragma unroll
    for (int s = 0; s < STAGES - 1; s++) {
        load_stage(s, s);
        CP_COMMIT();
    }

    // ldmatrix lane addressing
    const int a_row = lid & 15;            // row within 16-row tile
    const int a_khalf = (lid >> 4) * 8;    // 0 or 8 (k halves)
    const int b_nrow = ((lid >> 4) * 8) + (lid & 7);  // row within 16-n block
    const int b_khalf = ((lid >> 3) & 1) * 8;

    for (int kt = 0; kt < KT; kt++) {
        CP_WAIT(1);
        __syncthreads();

        const int nt = kt + STAGES - 1;
        if (nt < KT) load_stage(nt % STAGES, nt);
        CP_COMMIT();

        const int slot = kt % STAGES;
        const uint32_t sA = sb + slot * A_STAGE_BYTES;
        const uint32_t sBb = sb + STAGES * A_STAGE_BYTES + slot * B_STAGE_BYTES;

#pragma unroll
        for (int kk = 0; kk < 4; kk++) {        // 4 k-steps of 16
            const int kc = kk * 16;             // k half offset within stage
            uint32_t a[4][4];
#pragma unroll
            for (int mi = 0; mi < 4; mi++) {
                const int row = warp_m + mi * 16 + a_row;
                ldm_x4(a[mi][0], a[mi][1], a[mi][2], a[mi][3],
                       sA + SWZ(row * 128 + (kc + a_khalf) * 2));
            }
            uint32_t b[8][2];
#pragma unroll
            for (int j = 0; j < 4; j++) {       // each x4 covers 2 n-tiles
                const int row = warp_n + j * 16 + b_nrow;
                uint32_t r0, r1, r2, r3;
                ldm_x4(r0, r1, r2, r3,
                       sBb + SWZ(row * 128 + (kc + b_khalf) * 2));
                b[2 * j + 0][0] = r0; b[2 * j + 0][1] = r1;
                b[2 * j + 1][0] = r2; b[2 * j + 1][1] = r3;
            }
#pragma unroll
            for (int mi = 0; mi < 4; mi++)
#pragma unroll
                for (int ni = 0; ni < 8; ni++)
                    mma_16816(acc[mi][ni][0], acc[mi][ni][1], acc[mi][ni][2], acc[mi][ni][3],
                              a[mi][0], a[mi][1], a[mi][2], a[mi][3],
                              b[ni][0], b[ni][1]);
        }
        __syncthreads();
    }

    // ---- epilogue: scale by mean|W| and store ----
    const float sc = g_scale;
    const int er = lid >> 2;         // 0..7
    const int ec = (lid & 3) * 2;    // 0,2,4,6
#pragma unroll
    for (int mi = 0; mi < 4; mi++) {
        const int m_lo = m0 + warp_m + mi * 16 + er;
#pragma unroll
        for (int ni = 0; ni < 8; ni++) {
            const int n = n0 + warp_n + ni * 8 + ec;
            float2 v0 = make_float2(acc[mi][ni][0] * sc, acc[mi][ni][1] * sc);
            float2 v1 = make_float2(acc[mi][ni][2] * sc, acc[mi][ni][3] * sc);
            *reinterpret_cast<float2*>(out + (size_t)m_lo * NDIM + n) = v0;
            *reinterpret_cast<float2*>(out + (size_t)(m_lo + 8) * NDIM + n) = v1;
        }
    }
}

// ============================= host launch ===================================
extern "C" void kernel_launch(void* const* d_in, const int* in_sizes, int n_in,
                              void* d_out, int out_size) {
    const float* x = (const float*)d_in[0];
    const float* W = (const float*)d_in[1];
    float* out = (float*)d_out;

    k_reduce1<<<1024, 256>>>(W);
    k_reduce2<<<1, 256>>>();
    k_quant<<<2048, 256>>>((const float4*)W);
    k_xcvt<<<4096, 256>>>((const float4*)x);

    (void)cudaFuncSetAttribute(bitlinear_gemm, cudaFuncAttributeMaxDynamicSharedMemorySize, SMEM_TOTAL);
    bitlinear_gemm<<<dim3(NDIM / BN, MDIM / BM), 128, SMEM_TOTAL>>>(out);
}

// round 6
// speedup vs baseline: 1.0737x; 1.0033x over previous
#include <cuda_runtime.h>
#include <cuda_fp16.h>
#include <cstdint>

// ============================= problem constants =============================
#define MDIM 8192
#define NDIM 4096
#define KDIM 4096
#define W_ELEMS (NDIM * KDIM)
#define X_ELEMS (MDIM * KDIM)
#define EPSV 1e-5f

// ============================= GEMM tiling ===================================
// CTA 128x128, 4 warps (2M x 2N), warp tile 64x64, 3-stage cp.async pipeline,
// 2 CTAs/SM.
#define BM 128
#define BN 128
#define BK 64                    // halves per k-stage = 128 bytes per row
#define STAGES 3
#define KT (KDIM / BK)           // 64 k-stages
#define A_STAGE_BYTES (BM * BK * 2)   // 16384
#define B_STAGE_BYTES (BN * BK * 2)   // 16384
#define SMEM_TOTAL (STAGES * (A_STAGE_BYTES + B_STAGE_BYTES))   // 98304

// XOR swizzle for 128B rows: 16B chunk index ^= row%8
#define SWZ(byte) ((byte) ^ (((byte) >> 3) & 0x70))

// ============================= device scratch ================================
__device__ __half  g_Wqh[W_ELEMS];   // round(W/(mean|W|+eps)) as fp16 (exact ints)
__device__ __half  g_xh[X_ELEMS];    // x cast to fp16
__device__ double  g_partial[1024];
__device__ float   g_scale;          // mean(|W|)
__device__ float   g_den;            // mean(|W|) + eps
__device__ unsigned int g_count = 0; // last-block-done counter (self-resetting)

// ============================= asm helpers ===================================
__device__ __forceinline__ uint32_t smem_u32(const void* p) {
    uint32_t a;
    asm("{ .reg .u64 t; cvta.to.shared.u64 t, %1; cvt.u32.u64 %0, t; }" : "=r"(a) : "l"(p));
    return a;
}

__device__ __forceinline__ void cp_async16(uint32_t dst, const void* src) {
    asm volatile("cp.async.cg.shared.global [%0], [%1], 16;" :: "r"(dst), "l"(src));
}
#define CP_COMMIT() asm volatile("cp.async.commit_group;" ::: "memory")
#define CP_WAIT(N)  asm volatile("cp.async.wait_group %0;" :: "n"(N) : "memory")

__device__ __forceinline__ void ldm_x4(uint32_t& r0, uint32_t& r1, uint32_t& r2, uint32_t& r3,
                                       uint32_t addr) {
    asm volatile("ldmatrix.sync.aligned.m8n8.x4.shared.b16 {%0,%1,%2,%3}, [%4];"
                 : "=r"(r0), "=r"(r1), "=r"(r2), "=r"(r3) : "r"(addr));
}

__device__ __forceinline__ void mma_16816(float& c0, float& c1, float& c2, float& c3,
                                          uint32_t a0, uint32_t a1, uint32_t a2, uint32_t a3,
                                          uint32_t b0, uint32_t b1) {
    asm volatile("mma.sync.aligned.m16n8k16.row.col.f32.f16.f16.f32 "
                 "{%0,%1,%2,%3}, {%4,%5,%6,%7}, {%8,%9}, {%0,%1,%2,%3};"
                 : "+f"(c0), "+f"(c1), "+f"(c2), "+f"(c3)
                 : "r"(a0), "r"(a1), "r"(a2), "r"(a3), "r"(b0), "r"(b1));
}

// ============================= preprocessing =================================
// Fused two-stage mean|W| reduction: grid-sized partial sums + last-block final
// reduce (atomic counter, deterministic order, self-resetting -> replay safe).
__global__ void k_reduce(const float* __restrict__ W) {
    __shared__ double sdata[256];
    __shared__ bool is_last;
    double s = 0.0;
    for (int i = blockIdx.x * 256 + threadIdx.x; i < W_ELEMS; i += 256 * 1024)
        s += (double)fabsf(W[i]);
    sdata[threadIdx.x] = s;
    __syncthreads();
    for (int o = 128; o > 0; o >>= 1) {
        if (threadIdx.x < o) sdata[threadIdx.x] += sdata[threadIdx.x + o];
        __syncthreads();
    }
    if (threadIdx.x == 0) {
        g_partial[blockIdx.x] = sdata[0];
        __threadfence();
        is_last = (atomicAdd(&g_count, 1u) == gridDim.x - 1);
    }
    __syncthreads();
    if (is_last) {
        double t = 0.0;
        for (int i = threadIdx.x; i < 1024; i += 256) t += g_partial[i];
        sdata[threadIdx.x] = t;
        __syncthreads();
        for (int o = 128; o > 0; o >>= 1) {
            if (threadIdx.x < o) sdata[threadIdx.x] += sdata[threadIdx.x + o];
            __syncthreads();
        }
        if (threadIdx.x == 0) {
            float sc = (float)(sdata[0] / (double)W_ELEMS);
            g_scale = sc;
            g_den = sc + EPSV;
            g_count = 0;           // reset for next replay
        }
    }
}

// Wq = round_half_even(W / (mean|W|+eps)) -> fp16 (exact: small integers)
__global__ void k_quant(const float4* __restrict__ W4) {
    const float den = g_den;
    __half2* out2 = reinterpret_cast<__half2*>(g_Wqh);
    const int n4 = W_ELEMS / 4;
    for (int i = blockIdx.x * blockDim.x + threadIdx.x; i < n4; i += gridDim.x * blockDim.x) {
        float4 w = W4[i];
        out2[2 * i + 0] = __floats2half2_rn(rintf(w.x / den), rintf(w.y / den));
        out2[2 * i + 1] = __floats2half2_rn(rintf(w.z / den), rintf(w.w / den));
    }
}

// x -> fp16
__global__ void k_xcvt(const float4* __restrict__ X4) {
    __half2* out2 = reinterpret_cast<__half2*>(g_xh);
    const int n4 = X_ELEMS / 4;
    for (int i = blockIdx.x * blockDim.x + threadIdx.x; i < n4; i += gridDim.x * blockDim.x) {
        float4 v = X4[i];
        out2[2 * i + 0] = __floats2half2_rn(v.x, v.y);
        out2[2 * i + 1] = __floats2half2_rn(v.z, v.w);
    }
}

// ============================= GEMM kernel ===================================
__global__ void __launch_bounds__(128, 2) bitlinear_gemm(float* __restrict__ out) {
    extern __shared__ char smem[];
    const uint32_t sb = smem_u32(smem);
    const int tid = threadIdx.x;
    const int wid = tid >> 5;
    const int lid = tid & 31;

    const int m0 = blockIdx.y * BM;
    const int n0 = blockIdx.x * BN;
    const int warp_m = (wid >> 1) * 64;   // 2 warps in M
    const int warp_n = (wid & 1) * 64;    // 2 warps in N

    const __half* __restrict__ gA = g_xh;
    const __half* __restrict__ gB = g_Wqh;

    auto load_stage = [&](int slot, int kt) {
        const uint32_t sA = sb + slot * A_STAGE_BYTES;
        const uint32_t sBb = sb + STAGES * A_STAGE_BYTES + slot * B_STAGE_BYTES;
        const int kh = kt * BK;
#pragma unroll
        for (int i = 0; i < 8; i++) {
            const int ch = tid + i * 128;
            const int row = ch >> 3;
            const int cc = ch & 7;
            cp_async16(sA + SWZ(row * 128 + cc * 16),
                       gA + (size_t)(m0 + row) * KDIM + kh + cc * 8);
        }
#pragma unroll
        for (int i = 0; i < 8; i++) {
            const int ch = tid + i * 128;
            const int row = ch >> 3;
            const int cc = ch & 7;
            cp_async16(sBb + SWZ(row * 128 + cc * 16),
                       gB + (size_t)(n0 + row) * KDIM + kh + cc * 8);
        }
    };

    float acc[4][8][4];
#pragma unroll
    for (int mi = 0; mi < 4; mi++)
#pragma unroll
        for (int ni = 0; ni < 8; ni++)
#pragma unroll
            for (int q = 0; q < 4; q++) acc[mi][ni][q] = 0.0f;

#pragma unroll
    for (int s = 0; s < STAGES - 1; s++) {
        load_stage(s, s);
        CP_COMMIT();
    }

    const int a_row = lid & 15;
    const int a_khalf = (lid >> 4) * 8;
    const int b_nrow = ((lid >> 4) * 8) + (lid & 7);
    const int b_khalf = ((lid >> 3) & 1) * 8;

    for (int kt = 0; kt < KT; kt++) {
        CP_WAIT(1);
        __syncthreads();   // sole barrier: covers cp.async visibility (reads of
                           // slot kt%3) AND WAR safety for writes to (kt-1)%3,
                           // since all warps' iter kt-1 MMAs precede this point.

        const int nt = kt + STAGES - 1;
        if (nt < KT) load_stage(nt % STAGES, nt);
        CP_COMMIT();

        const int slot = kt % STAGES;
        const uint32_t sA = sb + slot * A_STAGE_BYTES;
        const uint32_t sBb = sb + STAGES * A_STAGE_BYTES + slot * B_STAGE_BYTES;

#pragma unroll
        for (int kk = 0; kk < 4; kk++) {
            const int kc = kk * 16;
            uint32_t a[4][4];
#pragma unroll
            for (int mi = 0; mi < 4; mi++) {
                const int row = warp_m + mi * 16 + a_row;
                ldm_x4(a[mi][0], a[mi][1], a[mi][2], a[mi][3],
                       sA + SWZ(row * 128 + (kc + a_khalf) * 2));
            }
            uint32_t b[8][2];
#pragma unroll
            for (int j = 0; j < 4; j++) {
                const int row = warp_n + j * 16 + b_nrow;
                uint32_t r0, r1, r2, r3;
                ldm_x4(r0, r1, r2, r3,
                       sBb + SWZ(row * 128 + (kc + b_khalf) * 2));
                b[2 * j + 0][0] = r0; b[2 * j + 0][1] = r1;
                b[2 * j + 1][0] = r2; b[2 * j + 1][1] = r3;
            }
#pragma unroll
            for (int mi = 0; mi < 4; mi++)
#pragma unroll
                for (int ni = 0; ni < 8; ni++)
                    mma_16816(acc[mi][ni][0], acc[mi][ni][1], acc[mi][ni][2], acc[mi][ni][3],
                              a[mi][0], a[mi][1], a[mi][2], a[mi][3],
                              b[ni][0], b[ni][1]);
        }
        // NOTE: no bottom __syncthreads() — see barrier comment above.
    }

    // ---- epilogue: scale by mean|W| and store ----
    const float sc = g_scale;
    const int er = lid >> 2;
    const int ec = (lid & 3) * 2;
#pragma unroll
    for (int mi = 0; mi < 4; mi++) {
        const int m_lo = m0 + warp_m + mi * 16 + er;
#pragma unroll
        for (int ni = 0; ni < 8; ni++) {
            const int n = n0 + warp_n + ni * 8 + ec;
            float2 v0 = make_float2(acc[mi][ni][0] * sc, acc[mi][ni][1] * sc);
            float2 v1 = make_float2(acc[mi][ni][2] * sc, acc[mi][ni][3] * sc);
            *reinterpret_cast<float2*>(out + (size_t)m_lo * NDIM + n) = v0;
            *reinterpret_cast<float2*>(out + (size_t)(m_lo + 8) * NDIM + n) = v1;
        }
    }
}

// ============================= host launch ===================================
extern "C" void kernel_launch(void* const* d_in, const int* in_sizes, int n_in,
                              void* d_out, int out_size) {
    const float* x = (const float*)d_in[0];
    const float* W = (const float*)d_in[1];
    float* out = (float*)d_out;

    k_reduce<<<1024, 256>>>(W);                 // launch 1
    k_quant<<<2048, 256>>>((const float4*)W);   // launch 2
    k_xcvt<<<4096, 256>>>((const float4*)x);    // launch 3

    (void)cudaFuncSetAttribute(bitlinear_gemm, cudaFuncAttributeMaxDynamicSharedMemorySize, SMEM_TOTAL);
    bitlinear_gemm<<<dim3(NDIM / BN, MDIM / BM), 128, SMEM_TOTAL>>>(out);  // launch 4
}